// round 5
// baseline (speedup 1.0000x reference)
#include <cuda_runtime.h>
#include <math.h>

#define NN   4096   // nodes
#define INF_ 512    // in features
#define NH   8      // heads
#define DH   64     // per-head dim
#define HD   512    // NH*DH

// Scratch (device globals — no allocations allowed)
__device__ float g_mx[NN * HD];   // projected features, [n][h*64+d]
__device__ float g_P [NN * HD];   // E[h,n] * mx[n][c]
__device__ float g_E [NH * NN];   // exp(t[h,n])

// ---------------------------------------------------------------------------
// GEMM: mx = x @ Wcat.  Wcat[f][h*64+d] = W[h][f][d].
// BM=64, BN=64, BK=16, 256 threads, 4x4 micro-tile. BN tile == one head.
// ---------------------------------------------------------------------------
__global__ __launch_bounds__(256) void gemm_kernel(const float* __restrict__ x,
                                                   const float* __restrict__ W)
{
    __shared__ float As[16][64];   // [k][m]
    __shared__ float Bs[16][64];   // [k][n]

    const int m0 = blockIdx.y * 64;
    const int n0 = blockIdx.x * 64;          // head-aligned
    const int h  = n0 >> 6;
    const float* __restrict__ Wh = W + (size_t)h * INF_ * DH;  // [512][64]

    const int tid = threadIdx.x;
    const int am = tid >> 2;                 // 0..63
    const int ak = (tid & 3) * 4;            // 0,4,8,12
    const int bk = tid >> 4;                 // 0..15
    const int bn = (tid & 15) * 4;           // 0..60
    const int tm = (tid >> 4) * 4;           // 0..60
    const int tn = (tid & 15) * 4;           // 0..60

    float acc[4][4] = {};

    for (int k0 = 0; k0 < INF_; k0 += 16) {
        float4 av = *(const float4*)(x  + (size_t)(m0 + am) * INF_ + k0 + ak);
        float4 bv = *(const float4*)(Wh + (size_t)(k0 + bk) * DH + bn);
        __syncthreads();
        As[ak + 0][am] = av.x; As[ak + 1][am] = av.y;
        As[ak + 2][am] = av.z; As[ak + 3][am] = av.w;
        *(float4*)&Bs[bk][bn] = bv;
        __syncthreads();
        #pragma unroll
        for (int k = 0; k < 16; k++) {
            float4 a = *(const float4*)&As[k][tm];
            float4 b = *(const float4*)&Bs[k][tn];
            acc[0][0] += a.x*b.x; acc[0][1] += a.x*b.y; acc[0][2] += a.x*b.z; acc[0][3] += a.x*b.w;
            acc[1][0] += a.y*b.x; acc[1][1] += a.y*b.y; acc[1][2] += a.y*b.z; acc[1][3] += a.y*b.w;
            acc[2][0] += a.z*b.x; acc[2][1] += a.z*b.y; acc[2][2] += a.z*b.z; acc[2][3] += a.z*b.w;
            acc[3][0] += a.w*b.x; acc[3][1] += a.w*b.y; acc[3][2] += a.w*b.z; acc[3][3] += a.w*b.w;
        }
    }
    #pragma unroll
    for (int i = 0; i < 4; i++) {
        float4 v = make_float4(acc[i][0], acc[i][1], acc[i][2], acc[i][3]);
        *(float4*)(g_mx + (size_t)(m0 + tm + i) * HD + n0 + tn) = v;
    }
}

// ---------------------------------------------------------------------------
// E/P kernel: per node n, t[h] = sum_d mx[n][h*64+d]*a_dst[h][d];
// E = exp(t); P[n][c] = E[c/64] * mx[n][c].
// ---------------------------------------------------------------------------
__global__ __launch_bounds__(512) void ep_kernel(const float* __restrict__ a_dst)
{
    const int n   = blockIdx.x;
    const int tid = threadIdx.x;            // == column c
    const float v = g_mx[(size_t)n * HD + tid];
    float p = v * a_dst[tid];

    #pragma unroll
    for (int o = 16; o > 0; o >>= 1) p += __shfl_xor_sync(0xFFFFFFFFu, p, o);

    __shared__ float ws[16];
    __shared__ float Eh[8];
    const int w = tid >> 5;
    if ((tid & 31) == 0) ws[w] = p;
    __syncthreads();
    if (tid < 8) {
        float t = ws[2 * tid] + ws[2 * tid + 1];
        float e = expf(t);                  // no max-shift needed: |t| small; s_i cancels
        Eh[tid] = e;
        g_E[tid * NN + n] = e;
    }
    __syncthreads();
    g_P[(size_t)n * HD + tid] = Eh[tid >> 6] * v;
}

// ---------------------------------------------------------------------------
// Attention kernel: one block per row i.
// Phase A: deterministic warp-ballot compaction of adj[i,:] into a list.
// Phase B: out[i][c] = sum_j P[j][c] / sum_j E[h][j].
// ---------------------------------------------------------------------------
__global__ __launch_bounds__(512) void attn_kernel(const float* __restrict__ adj,
                                                   float* __restrict__ out)
{
    const int i    = blockIdx.x;
    const int tid  = threadIdx.x;           // 512 threads
    const int lane = tid & 31;
    const int w    = tid >> 5;              // 16 warps

    __shared__ int list[NN];
    __shared__ int woff[17];

    const float* __restrict__ arow = adj + (size_t)i * NN;
    const int base = w * 256;

    // pass 1: per-warp counts (ordered)
    int cnt = 0;
    #pragma unroll
    for (int j0 = 0; j0 < 256; j0 += 32) {
        float a = arow[base + j0 + lane];
        unsigned m = __ballot_sync(0xFFFFFFFFu, a > 0.f);
        cnt += __popc(m);
    }
    if (lane == 0) woff[w + 1] = cnt;
    __syncthreads();
    if (tid == 0) {
        woff[0] = 0;
        #pragma unroll
        for (int k = 1; k <= 16; k++) woff[k] += woff[k - 1];
    }
    __syncthreads();

    // pass 2: compacted write (adj row is L1-resident from pass 1)
    int off = woff[w];
    #pragma unroll
    for (int j0 = 0; j0 < 256; j0 += 32) {
        int j = base + j0 + lane;
        float a = arow[j];
        unsigned m = __ballot_sync(0xFFFFFFFFu, a > 0.f);
        if (a > 0.f) list[off + __popc(m & ((1u << lane) - 1u))] = j;
        off += __popc(m);
    }
    __syncthreads();

    const int total = woff[16];
    const int c = tid;
    const int h = tid >> 6;
    const float* __restrict__ Erow = g_E + (size_t)h * NN;

    float acc = 0.f, ea = 0.f;
    int k = 0;
    for (; k + 4 <= total; k += 4) {
        int j0 = list[k], j1 = list[k + 1], j2 = list[k + 2], j3 = list[k + 3];
        float p0 = g_P[(size_t)j0 * HD + c];
        float p1 = g_P[(size_t)j1 * HD + c];
        float p2 = g_P[(size_t)j2 * HD + c];
        float p3 = g_P[(size_t)j3 * HD + c];
        float e0 = Erow[j0], e1 = Erow[j1], e2 = Erow[j2], e3 = Erow[j3];
        acc += (p0 + p1) + (p2 + p3);
        ea  += (e0 + e1) + (e2 + e3);
    }
    for (; k < total; k++) {
        int j = list[k];
        acc += g_P[(size_t)j * HD + c];
        ea  += Erow[j];
    }
    out[(size_t)i * HD + c] = acc / ea;
}

// ---------------------------------------------------------------------------
extern "C" void kernel_launch(void* const* d_in, const int* in_sizes, int n_in,
                              void* d_out, int out_size)
{
    const float* x      = (const float*)d_in[0];   // [4096, 512]
    const float* adj    = (const float*)d_in[1];   // [4096, 4096]
    const float* W      = (const float*)d_in[2];   // [8, 512, 64]
    // d_in[3] = a_origin — cancels in the softmax, unused
    const float* a_dst  = (const float*)d_in[4];   // [8, 64]
    float* out = (float*)d_out;                    // [4096, 512]

    gemm_kernel<<<dim3(HD / 64, NN / 64), 256>>>(x, W);
    ep_kernel<<<NN, 512>>>(a_dst);
    attn_kernel<<<NN, 512>>>(adj, out);
}

// round 7
// speedup vs baseline: 1.3604x; 1.3604x over previous
#include <cuda_runtime.h>
#include <cuda_bf16.h>
#include <stdint.h>
#include <math.h>

#define NN   4096   // nodes
#define INF_ 512    // in features
#define NH   8      // heads
#define DH   64     // per-head dim
#define HD   512    // NH*DH

// ---------------- scratch (device globals; no allocations allowed) ----------
__device__ float g_mx[NN * HD];            // projected features [n][c]
__device__ float g_P [NN * HD];            // E[h,n] * mx[n][c]
__device__ float g_E [NH * NN];            // exp(t[h,n])
__device__ __nv_bfloat16 g_xhi[NN * INF_]; // bf16 hi part of x
__device__ __nv_bfloat16 g_xlo[NN * INF_]; // bf16 lo residual of x
__device__ __nv_bfloat16 g_Whi[HD * INF_]; // B-layout [n][k] = W[h][k][d], hi
__device__ __nv_bfloat16 g_Wlo[HD * INF_]; // lo residual

// ---------------- PTX helpers (no tcgen05 — unsupported at this PTX target) -
__device__ __forceinline__ uint32_t smem_u32(const void* p) {
    uint32_t a;
    asm("{ .reg .u64 t; cvta.to.shared.u64 t, %1; cvt.u32.u64 %0, t; }"
        : "=r"(a) : "l"(p));
    return a;
}
#define CP16(dst, src)  asm volatile("cp.async.cg.shared.global [%0], [%1], 16;" :: "r"(dst), "l"(src) : "memory")
#define CP_COMMIT()     asm volatile("cp.async.commit_group;" ::: "memory")
#define CP_WAIT1()      asm volatile("cp.async.wait_group 1;" ::: "memory")
#define CP_WAIT0()      asm volatile("cp.async.wait_group 0;" ::: "memory")

#define LDSM4(r0, r1, r2, r3, a)                                               \
    asm volatile("ldmatrix.sync.aligned.m8n8.x4.shared.b16 {%0,%1,%2,%3}, [%4];" \
        : "=r"(r0), "=r"(r1), "=r"(r2), "=r"(r3) : "r"(a))

#define MMA(d, a, b)                                                           \
    asm volatile("mma.sync.aligned.m16n8k16.row.col.f32.bf16.bf16.f32 "        \
        "{%0,%1,%2,%3}, {%4,%5,%6,%7}, {%8,%9}, {%0,%1,%2,%3};"                \
        : "+f"((d)[0]), "+f"((d)[1]), "+f"((d)[2]), "+f"((d)[3])               \
        : "r"((a)[0]), "r"((a)[1]), "r"((a)[2]), "r"((a)[3]),                  \
          "r"((b)[0]), "r"((b)[1]))

// ---------------------------------------------------------------------------
// Conversion kernels: fp32 -> bf16 hi/lo split
// ---------------------------------------------------------------------------
__global__ __launch_bounds__(512) void conv_x(const float4* __restrict__ x) {
    int idx = blockIdx.x * 512 + threadIdx.x;        // float4 index
    float4 v = x[idx];
    int b = idx * 4;
    __nv_bfloat16 h0 = __float2bfloat16(v.x), h1 = __float2bfloat16(v.y);
    __nv_bfloat16 h2 = __float2bfloat16(v.z), h3 = __float2bfloat16(v.w);
    g_xhi[b+0]=h0; g_xhi[b+1]=h1; g_xhi[b+2]=h2; g_xhi[b+3]=h3;
    g_xlo[b+0]=__float2bfloat16(v.x-__bfloat162float(h0));
    g_xlo[b+1]=__float2bfloat16(v.y-__bfloat162float(h1));
    g_xlo[b+2]=__float2bfloat16(v.z-__bfloat162float(h2));
    g_xlo[b+3]=__float2bfloat16(v.w-__bfloat162float(h3));
}

// B layout: g_W*[n][k] = W[h=n>>6][f=k][d=n&63]
__global__ __launch_bounds__(512) void conv_w(const float* __restrict__ W) {
    int n = blockIdx.x, k = threadIdx.x;
    float v = W[((size_t)(n >> 6) * INF_ + k) * DH + (n & 63)];
    __nv_bfloat16 h = __float2bfloat16(v);
    g_Whi[n * INF_ + k] = h;
    g_Wlo[n * INF_ + k] = __float2bfloat16(v - __bfloat162float(h));
}

// ---------------------------------------------------------------------------
// HMMA bf16 GEMM: g_mx = xhi*Whi + xlo*Whi + xhi*Wlo (fp32 accumulators)
// Tile 128x128, BK=32, double-buffered cp.async, 8 warps (4x2 of 32x64).
// SMEM per buffer: 4 tiles (XHI, XLO, WHI, WLO), rows padded to 40 bf16.
// ---------------------------------------------------------------------------
#define TILEB   10240      // 128 rows * 80 bytes
#define BUFB    40960      // 4 tiles
#define GSMEM   81920      // 2 buffers
#define NC      16         // K chunks (512 / 32)

__global__ __launch_bounds__(256, 1) void gemm_hmma() {
    extern __shared__ char smem[];
    const uint32_t sb = smem_u32(smem);
    const int tid  = threadIdx.x;
    const int lane = tid & 31;
    const int m0 = blockIdx.y * 128, n0 = blockIdx.x * 128;

    const int wr = tid >> 6;           // warp row 0..3
    const int wc = (tid >> 5) & 1;     // warp col 0..1

    // ldmatrix per-lane byte offsets inside a tile
    const uint32_t aLane = (uint32_t)((wr * 32 + (lane & 15)) * 80 + (lane >> 4) * 16);
    const uint32_t bLane = (uint32_t)((wc * 64 + (lane & 7) + ((lane >> 4) << 3)) * 80
                                      + ((lane >> 3) & 1) * 16);

    // cp.async per-thread mapping: row = tid>>1, 32B segment = tid&1
    const int lrow = tid >> 1, lseg = tid & 1;
    const uint32_t so = (uint32_t)(lrow * 80 + lseg * 32);

    auto load_chunk = [&](int c) {
        const int kk = c * 32;
        const uint32_t bufb = sb + (c & 1) * BUFB;
        const __nv_bfloat16* xs = g_xhi + (size_t)(m0 + lrow) * INF_ + kk + lseg * 16;
        const __nv_bfloat16* xl = g_xlo + (size_t)(m0 + lrow) * INF_ + kk + lseg * 16;
        const __nv_bfloat16* wh = g_Whi + (size_t)(n0 + lrow) * INF_ + kk + lseg * 16;
        const __nv_bfloat16* wl = g_Wlo + (size_t)(n0 + lrow) * INF_ + kk + lseg * 16;
        CP16(bufb + so,                xs);  CP16(bufb + so + 16,                xs + 8);
        CP16(bufb + TILEB + so,        xl);  CP16(bufb + TILEB + so + 16,        xl + 8);
        CP16(bufb + 2 * TILEB + so,    wh);  CP16(bufb + 2 * TILEB + so + 16,    wh + 8);
        CP16(bufb + 3 * TILEB + so,    wl);  CP16(bufb + 3 * TILEB + so + 16,    wl + 8);
        CP_COMMIT();
    };

    float acc[2][8][4] = {};

    load_chunk(0);
    load_chunk(1);

    for (int c = 0; c < NC; c++) {
        if (c >= NC - 2) CP_WAIT0(); else CP_WAIT1();
        __syncthreads();

        const uint32_t bufb = sb + (c & 1) * BUFB;
        const uint32_t ab = bufb + aLane;              // XHI base (+TILEB = XLO)
        const uint32_t bb = bufb + 2 * TILEB + bLane;  // WHI base (+TILEB = WLO)

        #pragma unroll
        for (int ks = 0; ks < 2; ks++) {
            uint32_t ah[2][4], al[2][4], bh[8][2], bl[8][2];
            #pragma unroll
            for (int mt = 0; mt < 2; mt++) {
                uint32_t o = ab + mt * 1280 + ks * 32;
                LDSM4(ah[mt][0], ah[mt][1], ah[mt][2], ah[mt][3], o);
                LDSM4(al[mt][0], al[mt][1], al[mt][2], al[mt][3], o + TILEB);
            }
            #pragma unroll
            for (int np = 0; np < 4; np++) {
                uint32_t o = bb + np * 1280 + ks * 32;
                LDSM4(bh[2*np][0], bh[2*np][1], bh[2*np+1][0], bh[2*np+1][1], o);
                LDSM4(bl[2*np][0], bl[2*np][1], bl[2*np+1][0], bl[2*np+1][1], o + TILEB);
            }
            #pragma unroll
            for (int mt = 0; mt < 2; mt++)
                #pragma unroll
                for (int nt = 0; nt < 8; nt++) {
                    MMA(acc[mt][nt], ah[mt], bh[nt]);   // hi * hi
                    MMA(acc[mt][nt], al[mt], bh[nt]);   // lo * hi
                    MMA(acc[mt][nt], ah[mt], bl[nt]);   // hi * lo
                }
        }
        __syncthreads();
        if (c + 2 < NC) load_chunk(c + 2);
    }

    // epilogue: D fragments -> g_mx
    #pragma unroll
    for (int mt = 0; mt < 2; mt++) {
        const int row = m0 + wr * 32 + mt * 16 + (lane >> 2);
        #pragma unroll
        for (int nt = 0; nt < 8; nt++) {
            const int col = n0 + wc * 64 + nt * 8 + (lane & 3) * 2;
            float2 v0 = make_float2(acc[mt][nt][0], acc[mt][nt][1]);
            float2 v1 = make_float2(acc[mt][nt][2], acc[mt][nt][3]);
            *(float2*)&g_mx[(size_t)row * HD + col]       = v0;
            *(float2*)&g_mx[(size_t)(row + 8) * HD + col] = v1;
        }
    }
}

// ---------------------------------------------------------------------------
// E/P kernel: t[h] = mx[n] . a_dst[h]; E = exp(t); P = E * mx
// ---------------------------------------------------------------------------
__global__ __launch_bounds__(512) void ep_kernel(const float* __restrict__ a_dst)
{
    const int n   = blockIdx.x;
    const int tid = threadIdx.x;            // == column c
    const float v = g_mx[(size_t)n * HD + tid];
    float p = v * a_dst[tid];

    #pragma unroll
    for (int o = 16; o > 0; o >>= 1) p += __shfl_xor_sync(0xFFFFFFFFu, p, o);

    __shared__ float ws[16];
    __shared__ float Eh[8];
    const int w = tid >> 5;
    if ((tid & 31) == 0) ws[w] = p;
    __syncthreads();
    if (tid < 8) {
        float t = ws[2 * tid] + ws[2 * tid + 1];
        float e = expf(t);                  // s_i cancels; |t| small, no max-shift
        Eh[tid] = e;
        g_E[tid * NN + n] = e;
    }
    __syncthreads();
    g_P[(size_t)n * HD + tid] = Eh[tid >> 6] * v;
}

// ---------------------------------------------------------------------------
// Attention: one block per row i. Single-pass float4 compaction, then gather.
// ---------------------------------------------------------------------------
__global__ __launch_bounds__(512) void attn_kernel(const float* __restrict__ adj,
                                                   float* __restrict__ out)
{
    const int i    = blockIdx.x;
    const int tid  = threadIdx.x;           // 512 threads
    const int lane = tid & 31;
    const int w    = tid >> 5;              // 16 warps, 256 elems each

    __shared__ int list[NN];
    __shared__ int woff[17];

    const float4* __restrict__ arow4 = (const float4*)(adj + (size_t)i * NN);

    // single pass: load float4, ballot per component, keep in registers
    float4 v[2];
    unsigned m[2][4];
    int cnt = 0;
    #pragma unroll
    for (int it = 0; it < 2; it++) {
        v[it] = arow4[w * 64 + it * 32 + lane];
        m[it][0] = __ballot_sync(0xFFFFFFFFu, v[it].x > 0.f);
        m[it][1] = __ballot_sync(0xFFFFFFFFu, v[it].y > 0.f);
        m[it][2] = __ballot_sync(0xFFFFFFFFu, v[it].z > 0.f);
        m[it][3] = __ballot_sync(0xFFFFFFFFu, v[it].w > 0.f);
        cnt += __popc(m[it][0]) + __popc(m[it][1]) + __popc(m[it][2]) + __popc(m[it][3]);
    }
    if (lane == 0) woff[w + 1] = cnt;
    __syncthreads();
    if (tid == 0) {
        woff[0] = 0;
        #pragma unroll
        for (int k = 1; k <= 16; k++) woff[k] += woff[k - 1];
    }
    __syncthreads();

    // compacted write from registers (ascending j within each warp range)
    {
        int off = woff[w];
        const unsigned lt = (1u << lane) - 1u;
        #pragma unroll
        for (int it = 0; it < 2; it++) {
            int rr = off + __popc(m[it][0] & lt) + __popc(m[it][1] & lt)
                         + __popc(m[it][2] & lt) + __popc(m[it][3] & lt);
            int bj = (w * 64 + it * 32 + lane) * 4;
            if (v[it].x > 0.f) list[rr++] = bj;
            if (v[it].y > 0.f) list[rr++] = bj + 1;
            if (v[it].z > 0.f) list[rr++] = bj + 2;
            if (v[it].w > 0.f) list[rr++] = bj + 3;
            off += __popc(m[it][0]) + __popc(m[it][1]) + __popc(m[it][2]) + __popc(m[it][3]);
        }
    }
    __syncthreads();

    const int total = woff[16];
    const int c = tid;
    const int h = tid >> 6;
    const float* __restrict__ Erow = g_E + (size_t)h * NN;

    float acc = 0.f, ea = 0.f;
    int k = 0;
    for (; k + 4 <= total; k += 4) {
        int j0 = list[k], j1 = list[k + 1], j2 = list[k + 2], j3 = list[k + 3];
        float p0 = g_P[(size_t)j0 * HD + c];
        float p1 = g_P[(size_t)j1 * HD + c];
        float p2 = g_P[(size_t)j2 * HD + c];
        float p3 = g_P[(size_t)j3 * HD + c];
        float e0 = Erow[j0], e1 = Erow[j1], e2 = Erow[j2], e3 = Erow[j3];
        acc += (p0 + p1) + (p2 + p3);
        ea  += (e0 + e1) + (e2 + e3);
    }
    for (; k < total; k++) {
        int j = list[k];
        acc += g_P[(size_t)j * HD + c];
        ea  += Erow[j];
    }
    out[(size_t)i * HD + c] = acc / ea;
}

// ---------------------------------------------------------------------------
extern "C" void kernel_launch(void* const* d_in, const int* in_sizes, int n_in,
                              void* d_out, int out_size)
{
    const float* x     = (const float*)d_in[0];   // [4096, 512]
    const float* adj   = (const float*)d_in[1];   // [4096, 4096]
    const float* W     = (const float*)d_in[2];   // [8, 512, 64]
    // d_in[3] = a_origin — cancels in the row-wise softmax, unused
    const float* a_dst = (const float*)d_in[4];   // [8, 64]
    float* out = (float*)d_out;                   // [4096, 512]

    cudaFuncSetAttribute(gemm_hmma, cudaFuncAttributeMaxDynamicSharedMemorySize,
                         GSMEM);

    conv_x<<<(NN * INF_ / 4) / 512, 512>>>((const float4*)x);
    conv_w<<<HD, 512>>>(W);
    gemm_hmma<<<dim3(HD / 128, NN / 128), 256, GSMEM>>>();
    ep_kernel<<<NN, 512>>>(a_dst);
    attn_kernel<<<NN, 512>>>(adj, out);
}